// round 11
// baseline (speedup 1.0000x reference)
#include <cuda_runtime.h>

// LSTM_46316927320185 — R11: vocab table + 2-elems-per-lane recurrence (4 elems/warp)
// B=4096, T=512, EMB=32, HID=16, VOCAB=50000.
//
// R9 (180.8us; recur 153.8): stall-bound — 3.5 single-chain warps/SMSP left
// ~50% of issue slots empty (issue 48.8%). R11 packs 2 batch elements per
// LANE (warp = 4 elems; group eh owns elems {2eh,2eh+1}):
//  - 2 independent dependency chains per warp -> compiler fills tanh/LDS
//    stall slots; chains/SMSP = 4.
//  - per-elem instr cost unchanged (no merges; STS/syncwarp amortized);
//    wk registers shared across the lane's 2 elems.
//  - grid 128 x 256thr (8 warps, 32 elems) = 4096 exactly, zero tail;
//    uniform 2 warps/SMSP on active SMs.
// Table phase unchanged: 12.8MB gate-preactivation table (i,f,o pre-halved),
// L2-resident, gathered per step.

#define HID    16
#define EMB    32
#define T_LEN  512
#define BATCH  4096
#define VOCAB  50000

typedef unsigned long long u64;

// [v*HID + j] -> float4 (xp_i/2, xp_f/2, xp_g, xp_o/2), biases folded. 12.8 MB.
__device__ float4 g_tbl[(size_t)VOCAB * HID];

__device__ __forceinline__ u64 fma2(u64 a, u64 b, u64 c) {
    u64 d; asm("fma.rn.f32x2 %0, %1, %2, %3;" : "=l"(d) : "l"(a), "l"(b), "l"(c)); return d;
}
__device__ __forceinline__ u64 mul2(u64 a, u64 b) {
    u64 d; asm("mul.rn.f32x2 %0, %1, %2;" : "=l"(d) : "l"(a), "l"(b)); return d;
}
__device__ __forceinline__ u64 rep2(float v) {
    u64 r; asm("mov.b64 %0, {%1, %1};" : "=l"(r) : "f"(v)); return r;
}
__device__ __forceinline__ void unpack2(u64 v, float& lo, float& hi) {
    asm("mov.b64 {%0, %1}, %2;" : "=f"(lo), "=f"(hi) : "l"(v));
}
__device__ __forceinline__ float hadd2(u64 v) {
    float lo, hi; unpack2(v, lo, hi); return lo + hi;
}
__device__ __forceinline__ float tanh_ap(float x) {
    float y; asm("tanh.approx.f32 %0, %1;" : "=f"(y) : "f"(x)); return y;
}

// ============ Phase A: per-vocab projection table ============
#define PT_THREADS 256
#define PT_GRID    ((VOCAB * HID) / PT_THREADS)   // 3125

__global__ __launch_bounds__(PT_THREADS)
void proj_table_kernel(const float* __restrict__ embed,
                       const float* __restrict__ w_ih,
                       const float* __restrict__ b_ih,
                       const float* __restrict__ b_hh)
{
    // gate-packed transposed weights: [k*HID+j] = ((wi,wf),(wg,wo))
    __shared__ ulonglong2 w_u[EMB * HID];   // 8 KB

    const int tid = threadIdx.x;
    for (int i = tid; i < EMB * HID; i += PT_THREADS) {
        int k = i / HID, jj = i % HID;
        float4 w = make_float4(w_ih[(0 * HID + jj) * EMB + k],
                               w_ih[(1 * HID + jj) * EMB + k],
                               w_ih[(2 * HID + jj) * EMB + k],
                               w_ih[(3 * HID + jj) * EMB + k]);
        *(float4*)&w_u[i] = w;
    }
    __syncthreads();

    const int gid = blockIdx.x * PT_THREADS + tid;
    const int v = gid >> 4;        // vocab row
    const int j = gid & 15;        // hidden unit

    const float* er = embed + (size_t)v * EMB;
    u64 a01 = 0ull, a23 = 0ull;
    #pragma unroll
    for (int k = 0; k < EMB; ++k) {
        const u64 q = rep2(er[k]);              // broadcast across 16 j-lanes
        const ulonglong2 w = w_u[k * HID + j];
        a01 = fma2(q, w.x, a01);
        a23 = fma2(q, w.y, a23);
    }
    float ai, af, ag, ao;
    unpack2(a01, ai, af);
    unpack2(a23, ag, ao);
    // gates i,f,o pre-scaled by 0.5 (sigmoid identity); g unscaled (tanh)
    g_tbl[gid] = make_float4(0.5f * (ai + b_ih[j]           + b_hh[j]),
                             0.5f * (af + b_ih[HID + j]     + b_hh[HID + j]),
                                     ag + b_ih[2 * HID + j] + b_hh[2 * HID + j],
                             0.5f * (ao + b_ih[3 * HID + j] + b_hh[3 * HID + j]));
}

// ============ Phase B: recurrence — 4 elems/warp, 2 per lane ============
#define RC_WARPS   8
#define RC_THREADS 256
#define RC_EPW     4                   // elems per warp
#define RC_EPC     32                  // 8 warps * 4
#define RC_GRID    128                 // 128*32 = 4096 exactly, no tail

__global__ __launch_bounds__(RC_THREADS, 1)
void recur_kernel(const int*   __restrict__ x,
                  const float* __restrict__ w_hh,
                  const float* __restrict__ fc_w,
                  const float* __restrict__ fc_b,
                  float*       __restrict__ out)
{
    // double-buffered h staging: [buf][warp][local elem][j]  (16 KB)
    __shared__ float h_s[2][RC_WARPS][RC_EPW][HID];

    const int tid  = threadIdx.x;
    const int warp = tid >> 5, lane = tid & 31;
    const int eh   = lane >> 4;          // lane group: owns elems {2eh, 2eh+1}
    const int j    = lane & 15;          // hidden unit owned
    const int le0  = eh * 2;             // local elem base within warp
    const int b0   = blockIdx.x * RC_EPC + warp * RC_EPW + le0;

    // K-pair packed recurrent weights, SHARED by the lane's 2 elems:
    // wk[g][i] = (w[g,j,2i], w[g,j,2i+1]); gates i,f,o halved (sigmoid fold).
    u64 wk[4][8];
    #pragma unroll
    for (int g = 0; g < 4; ++g) {
        const u64* wr = (const u64*)(w_hh + (size_t)(g * HID + j) * HID);
        #pragma unroll
        for (int i = 0; i < 8; ++i) wk[g][i] = wr[i];
    }
    {
        const u64 hlf = rep2(0.5f);
        #pragma unroll
        for (int i = 0; i < 8; ++i) {
            wk[0][i] = mul2(wk[0][i], hlf);
            wk[1][i] = mul2(wk[1][i], hlf);
            wk[3][i] = mul2(wk[3][i], hlf);
        }
    }

    const int* xcol0 = x + (size_t)(b0 + 0) * T_LEN;
    const int* xcol1 = x + (size_t)(b0 + 1) * T_LEN;

    // gather pipeline per elem: rows for t (xc), t+1 (xn); index for t+2 (i2)
    float4 xc[2], xn[2];
    int    i2[2];
    xc[0] = g_tbl[(size_t)xcol0[0] * HID + j];
    xc[1] = g_tbl[(size_t)xcol1[0] * HID + j];
    xn[0] = g_tbl[(size_t)xcol0[1] * HID + j];
    xn[1] = g_tbl[(size_t)xcol1[1] * HID + j];
    i2[0] = xcol0[2];
    i2[1] = xcol1[2];

    float h[2] = {0.f, 0.f}, c[2] = {0.f, 0.f};

    #pragma unroll 2
    for (int t = 0; t < T_LEN; ++t) {
        const int buf = t & 1;
        h_s[buf][warp][le0 + 0][j] = h[0];
        h_s[buf][warp][le0 + 1][j] = h[1];
        __syncwarp();

        // kick next gathers early (t+2 rows; t+3 indices) — overlap with matvec
        const int tn = (t + 3 < T_LEN) ? (t + 3) : (T_LEN - 1);
        const float4 x2_0 = g_tbl[(size_t)i2[0] * HID + j];
        const float4 x2_1 = g_tbl[(size_t)i2[1] * HID + j];
        const int    i3_0 = xcol0[tn];
        const int    i3_1 = xcol1[tn];

        // two independent chains (elem 0 / elem 1) — compiler interleaves
        #pragma unroll
        for (int e = 0; e < 2; ++e) {
            const ulonglong2* hp = (const ulonglong2*)h_s[buf][warp][le0 + e];
            u64 a0 = 0ull, a1 = 0ull, a2 = 0ull, a3 = 0ull;
            #pragma unroll
            for (int i = 0; i < 4; ++i) {
                const ulonglong2 hv = hp[i];
                a0 = fma2(hv.x, wk[0][2 * i], a0); a0 = fma2(hv.y, wk[0][2 * i + 1], a0);
                a1 = fma2(hv.x, wk[1][2 * i], a1); a1 = fma2(hv.y, wk[1][2 * i + 1], a1);
                a2 = fma2(hv.x, wk[2][2 * i], a2); a2 = fma2(hv.y, wk[2][2 * i + 1], a2);
                a3 = fma2(hv.x, wk[3][2 * i], a3); a3 = fma2(hv.y, wk[3][2 * i + 1], a3);
            }
            const float si = hadd2(a0) + xc[e].x;   // pre-scaled by 0.5
            const float sf = hadd2(a1) + xc[e].y;
            const float sg = hadd2(a2) + xc[e].z;   // unscaled (tanh gate)
            const float so = hadd2(a3) + xc[e].w;

            const float ig = fmaf(tanh_ap(si), 0.5f, 0.5f);
            const float fg = fmaf(tanh_ap(sf), 0.5f, 0.5f);
            const float gg = tanh_ap(sg);
            const float og = fmaf(tanh_ap(so), 0.5f, 0.5f);
            c[e] = fg * c[e] + ig * gg;
            h[e] = og * tanh_ap(c[e]);
        }

        xc[0] = xn[0]; xn[0] = x2_0; i2[0] = i3_0;
        xc[1] = xn[1]; xn[1] = x2_1; i2[1] = i3_1;
    }

    // FC head: reduce over j within this 16-lane group (xor 8..1 stays in-group)
    const float fcw = fc_w[j];
    const float fcb = fc_b[0];
    #pragma unroll
    for (int e = 0; e < 2; ++e) {
        float v = h[e] * fcw;
        v += __shfl_xor_sync(0xffffffffu, v, 8);
        v += __shfl_xor_sync(0xffffffffu, v, 4);
        v += __shfl_xor_sync(0xffffffffu, v, 2);
        v += __shfl_xor_sync(0xffffffffu, v, 1);
        if (j == 0) out[b0 + e] = fmaf(tanh_ap(0.5f * (v + fcb)), 0.5f, 0.5f);
    }
}

extern "C" void kernel_launch(void* const* d_in, const int* in_sizes, int n_in,
                              void* d_out, int out_size)
{
    const int*   x     = (const int*)  d_in[0];
    const float* embed = (const float*)d_in[1];
    const float* w_ih  = (const float*)d_in[2];
    const float* w_hh  = (const float*)d_in[3];
    const float* b_ih  = (const float*)d_in[4];
    const float* b_hh  = (const float*)d_in[5];
    const float* fc_w  = (const float*)d_in[6];
    const float* fc_b  = (const float*)d_in[7];
    float* out = (float*)d_out;

    proj_table_kernel<<<PT_GRID, PT_THREADS>>>(embed, w_ih, b_ih, b_hh);
    recur_kernel<<<RC_GRID, RC_THREADS>>>(x, w_hh, fc_w, fc_b, out);
}